// round 10
// baseline (speedup 1.0000x reference)
#include <cuda_runtime.h>
#include <cstdint>

// Problem shape (fixed by the dataset)
#define BB 4
#define LL 2048
#define CC 1024

// Tiling: one warp per block, warp = G groups x CT channels
#define CT 2             // channels per block (lanes c = lane & 1)
#define G  16            // chunk groups (lanes g = lane >> 1)
#define EPT 2            // L elements per thread per piece
#define LP (G * EPT)     // 32 L elements per piece
#define THREADS (CT * G) // 32 (one warp)
#define PIECES (LL / LP) // 64

#define FULLMASK 0xffffffffu

// R = P @ Q (+ I), 2x2 complex matrices as float[8], layout [i][j][re/im]
__device__ __forceinline__ void cmm(const float* P, const float* Q, const float* I, float* R) {
#pragma unroll
    for (int i = 0; i < 2; i++) {
#pragma unroll
        for (int j = 0; j < 2; j++) {
            float re, im;
            if (I) { re = I[(i * 2 + j) * 2]; im = I[(i * 2 + j) * 2 + 1]; }
            else   { re = 0.f; im = 0.f; }
#pragma unroll
            for (int k = 0; k < 2; k++) {
                const float pr = P[(i * 2 + k) * 2], pi = P[(i * 2 + k) * 2 + 1];
                const float qr = Q[(k * 2 + j) * 2], qi = Q[(k * 2 + j) * 2 + 1];
                re = fmaf(pr, qr, re); re = fmaf(-pi, qi, re);
                im = fmaf(pr, qi, im); im = fmaf(pi, qr, im);
            }
            R[(i * 2 + j) * 2] = re;
            R[(i * 2 + j) * 2 + 1] = im;
        }
    }
}

__device__ __forceinline__ void cp8(const float* s, float* d) {
#pragma unroll
    for (int k = 0; k < 8; k++) d[k] = s[k];
}

struct Ctx {
    const float4* __restrict__ A4;
    const float4* __restrict__ X4;
    float4* __restrict__ Y4;
    int base;   // (b*LL)*(CC*2) + chan2  : f4 index of row 0 for this lane's channel
    int rowoff; // g*EPT rows offset contribution, folded into base
    int g;
};

// Load piece p's EPT elements for this thread into registers (streaming).
__device__ __forceinline__ void load_piece(const Ctx& ctx, int p,
                                           float (&Am)[EPT][8], float (&Xm)[EPT][8]) {
#pragma unroll
    for (int i = 0; i < EPT; i++) {
        const int idx = ctx.base + (p * LP + i) * (CC * 2);
        float4 a0 = __ldcs(&ctx.A4[idx]);
        float4 a1 = __ldcs(&ctx.A4[idx + 1]);
        float4 x0 = __ldcs(&ctx.X4[idx]);
        float4 x1 = __ldcs(&ctx.X4[idx + 1]);
        Am[i][0] = a0.x; Am[i][1] = a0.y; Am[i][2] = a0.z; Am[i][3] = a0.w;
        Am[i][4] = a1.x; Am[i][5] = a1.y; Am[i][6] = a1.z; Am[i][7] = a1.w;
        Xm[i][0] = x0.x; Xm[i][1] = x0.y; Xm[i][2] = x0.z; Xm[i][3] = x0.w;
        Xm[i][4] = x1.x; Xm[i][5] = x1.y; Xm[i][6] = x1.z; Xm[i][7] = x1.w;
    }
}

// Scan one piece (data already in registers), update carry, write output.
__device__ __forceinline__ void compute_piece(const Ctx& ctx, int p,
                                              float (&Am)[EPT][8], float (&Xm)[EPT][8],
                                              float (&carry)[8]) {
    const int g = ctx.g;

    // ---- per-thread serial aggregate over EPT elements ----
    float IA[8], IX[8];
    cp8(Am[0], IA); cp8(Xm[0], IX);
#pragma unroll
    for (int i = 1; i < EPT; i++) {
        float TA[8], TX[8];
        cmm(Am[i], IA, nullptr, TA);    // A_i @ IA
        cmm(Am[i], IX, Xm[i], TX);      // A_i @ IX + X_i
        cp8(TA, IA); cp8(TX, IX);
    }

    // ---- inclusive Kogge-Stone scan over the G groups (shuffle-based) ----
#pragma unroll
    for (int d = 1; d < G; d <<= 1) {
        float tA[8], tX[8];
#pragma unroll
        for (int k = 0; k < 8; k++) {
            tA[k] = __shfl_up_sync(FULLMASK, IA[k], d * CT);
            tX[k] = __shfl_up_sync(FULLMASK, IX[k], d * CT);
        }
        if (g >= d) {
            float nA[8], nX[8];
            cmm(IA, tA, nullptr, nA);   // A_later @ A_earlier
            cmm(IA, tX, IX, nX);        // A_later @ X_earlier + X_later
            cp8(nA, IA); cp8(nX, IX);
        }
    }

    // ---- exclusive prefix (lane g-1) and full-piece aggregate (lane G-1) ----
    const int c = threadIdx.x & (CT - 1);
    float EA[8], EX[8], FA[8], FX[8];
#pragma unroll
    for (int k = 0; k < 8; k++) {
        EA[k] = __shfl_up_sync(FULLMASK, IA[k], CT);
        EX[k] = __shfl_up_sync(FULLMASK, IX[k], CT);
        FA[k] = __shfl_sync(FULLMASK, IA[k], (G - 1) * CT + c);
        FX[k] = __shfl_sync(FULLMASK, IX[k], (G - 1) * CT + c);
    }

    // start value for this group's replay (uses OLD carry)
    float Yp[8];
    if (g == 0) {
        cp8(carry, Yp);
    } else {
        cmm(EA, carry, EX, Yp);         // A_{0..g-1} @ carry + X_{0..g-1}
    }

    // next piece's carry (uses OLD carry)
    {
        float nc[8];
        cmm(FA, carry, FX, nc);         // A_{0..G-1} @ carry + X_{0..G-1}
        cp8(nc, carry);
    }

    // ---- replay with carry, coalesced streaming stores ----
    float Y[8];
    cp8(Yp, Y);
#pragma unroll
    for (int i = 0; i < EPT; i++) {
        float T[8];
        cmm(Am[i], Y, Xm[i], T);
        cp8(T, Y);
        const int idx = ctx.base + (p * LP + i) * (CC * 2);
        __stcs(&ctx.Y4[idx],     make_float4(Y[0], Y[1], Y[2], Y[3]));
        __stcs(&ctx.Y4[idx + 1], make_float4(Y[4], Y[5], Y[6], Y[7]));
    }
}

__global__ void __launch_bounds__(THREADS)
pscan_kernel(const float* __restrict__ Ag, const float* __restrict__ Xg,
             float* __restrict__ Yg) {
    const int lane = threadIdx.x;
    const int c = lane & (CT - 1);
    const int g = lane >> 1;            // log2(CT) = 1
    const int b = blockIdx.y;
    const int c0 = blockIdx.x * CT;

    Ctx ctx;
    ctx.A4 = (const float4*)Ag;
    ctx.X4 = (const float4*)Xg;
    ctx.Y4 = (float4*)Yg;
    ctx.g = g;
    // f4 index of this lane's (channel, first-row-of-its-chunk) at piece 0
    ctx.base = (b * LL + g * EPT) * (CC * 2) + (c0 + c) * 2;

    float carry[8];
#pragma unroll
    for (int k = 0; k < 8; k++) carry[k] = 0.f;

    float A0[EPT][8], X0[EPT][8], A1[EPT][8], X1[EPT][8];

    // prologue: piece 0 into buf0
    load_piece(ctx, 0, A0, X0);

#pragma unroll 1
    for (int p = 0; p < PIECES; p += 2) {
        // prefetch p+1 into buf1 while computing p from buf0
        load_piece(ctx, p + 1, A1, X1);
        compute_piece(ctx, p, A0, X0, carry);
        // prefetch p+2 into buf0 while computing p+1 from buf1
        if (p + 2 < PIECES) load_piece(ctx, p + 2, A0, X0);
        compute_piece(ctx, p + 1, A1, X1, carry);
    }
}

extern "C" void kernel_launch(void* const* d_in, const int* in_sizes, int n_in,
                              void* d_out, int out_size) {
    const float* A = (const float*)d_in[0];
    const float* X = (const float*)d_in[1];
    float* Y = (float*)d_out;

    dim3 grid(CC / CT, BB);   // 512 x 4 = 2048 one-warp CTAs
    pscan_kernel<<<grid, THREADS>>>(A, X, Y);
}

// round 12
// speedup vs baseline: 1.3574x; 1.3574x over previous
#include <cuda_runtime.h>
#include <cstdint>

// Problem shape (fixed by the dataset)
#define BB 4
#define LL 2048
#define CC 1024

// Tiling: one warp per block, warp = G groups x CT channels
#define CT 4             // channels per block (lanes c = lane & 3)
#define G  8             // chunk groups (lanes g = lane >> 2)
#define EPT 4            // L elements per thread per piece
#define LP (G * EPT)     // 32 L elements per piece
#define THREADS (CT * G) // 32 (one warp)
#define PIECES (LL / LP) // 64

#define FULLMASK 0xffffffffu

// R = P @ Q (+ I), 2x2 complex matrices as float[8], layout [i][j][re/im]
__device__ __forceinline__ void cmm(const float* P, const float* Q, const float* I, float* R) {
#pragma unroll
    for (int i = 0; i < 2; i++) {
#pragma unroll
        for (int j = 0; j < 2; j++) {
            float re, im;
            if (I) { re = I[(i * 2 + j) * 2]; im = I[(i * 2 + j) * 2 + 1]; }
            else   { re = 0.f; im = 0.f; }
#pragma unroll
            for (int k = 0; k < 2; k++) {
                const float pr = P[(i * 2 + k) * 2], pi = P[(i * 2 + k) * 2 + 1];
                const float qr = Q[(k * 2 + j) * 2], qi = Q[(k * 2 + j) * 2 + 1];
                re = fmaf(pr, qr, re); re = fmaf(-pi, qi, re);
                im = fmaf(pr, qi, im); im = fmaf(pi, qr, im);
            }
            R[(i * 2 + j) * 2] = re;
            R[(i * 2 + j) * 2 + 1] = im;
        }
    }
}

__device__ __forceinline__ void cp8(const float* s, float* d) {
#pragma unroll
    for (int k = 0; k < 8; k++) d[k] = s[k];
}

struct Ctx {
    const float4* __restrict__ A4;
    const float4* __restrict__ X4;
    float4* __restrict__ Y4;
    int base;   // f4 index of (piece 0, this thread's first row, this channel)
    int g;
};

// Load piece p's EPT elements for this thread into registers (streaming).
__device__ __forceinline__ void load_piece(const Ctx& ctx, int p,
                                           float (&Am)[EPT][8], float (&Xm)[EPT][8]) {
#pragma unroll
    for (int i = 0; i < EPT; i++) {
        const int idx = ctx.base + (p * LP + i) * (CC * 2);
        float4 a0 = __ldcs(&ctx.A4[idx]);
        float4 a1 = __ldcs(&ctx.A4[idx + 1]);
        float4 x0 = __ldcs(&ctx.X4[idx]);
        float4 x1 = __ldcs(&ctx.X4[idx + 1]);
        Am[i][0] = a0.x; Am[i][1] = a0.y; Am[i][2] = a0.z; Am[i][3] = a0.w;
        Am[i][4] = a1.x; Am[i][5] = a1.y; Am[i][6] = a1.z; Am[i][7] = a1.w;
        Xm[i][0] = x0.x; Xm[i][1] = x0.y; Xm[i][2] = x0.z; Xm[i][3] = x0.w;
        Xm[i][4] = x1.x; Xm[i][5] = x1.y; Xm[i][6] = x1.z; Xm[i][7] = x1.w;
    }
}

// Scan one piece (data already in registers), update carry, write output.
__device__ __forceinline__ void compute_piece(const Ctx& ctx, int p,
                                              float (&Am)[EPT][8], float (&Xm)[EPT][8],
                                              float (&carry)[8]) {
    const int g = ctx.g;

    // ---- per-thread serial aggregate over EPT elements ----
    float IA[8], IX[8];
    cp8(Am[0], IA); cp8(Xm[0], IX);
#pragma unroll
    for (int i = 1; i < EPT; i++) {
        float TA[8], TX[8];
        cmm(Am[i], IA, nullptr, TA);    // A_i @ IA
        cmm(Am[i], IX, Xm[i], TX);      // A_i @ IX + X_i
        cp8(TA, IA); cp8(TX, IX);
    }

    // ---- inclusive Kogge-Stone scan over the G groups (shuffle-based) ----
#pragma unroll
    for (int d = 1; d < G; d <<= 1) {
        float tA[8], tX[8];
#pragma unroll
        for (int k = 0; k < 8; k++) {
            tA[k] = __shfl_up_sync(FULLMASK, IA[k], d * CT);
            tX[k] = __shfl_up_sync(FULLMASK, IX[k], d * CT);
        }
        if (g >= d) {
            float nA[8], nX[8];
            cmm(IA, tA, nullptr, nA);   // A_later @ A_earlier
            cmm(IA, tX, IX, nX);        // A_later @ X_earlier + X_later
            cp8(nA, IA); cp8(nX, IX);
        }
    }

    // ---- exclusive prefix (lane g-1) and full-piece aggregate (lane G-1) ----
    const int c = threadIdx.x & (CT - 1);
    float EA[8], EX[8], FA[8], FX[8];
#pragma unroll
    for (int k = 0; k < 8; k++) {
        EA[k] = __shfl_up_sync(FULLMASK, IA[k], CT);
        EX[k] = __shfl_up_sync(FULLMASK, IX[k], CT);
        FA[k] = __shfl_sync(FULLMASK, IA[k], (G - 1) * CT + c);
        FX[k] = __shfl_sync(FULLMASK, IX[k], (G - 1) * CT + c);
    }

    // start value for this group's replay (uses OLD carry)
    float Yp[8];
    if (g == 0) {
        cp8(carry, Yp);
    } else {
        cmm(EA, carry, EX, Yp);         // A_{0..g-1} @ carry + X_{0..g-1}
    }

    // next piece's carry (uses OLD carry)
    {
        float nc[8];
        cmm(FA, carry, FX, nc);         // A_{0..G-1} @ carry + X_{0..G-1}
        cp8(nc, carry);
    }

    // ---- replay with carry, coalesced streaming stores ----
    float Y[8];
    cp8(Yp, Y);
#pragma unroll
    for (int i = 0; i < EPT; i++) {
        float T[8];
        cmm(Am[i], Y, Xm[i], T);
        cp8(T, Y);
        const int idx = ctx.base + (p * LP + i) * (CC * 2);
        __stcs(&ctx.Y4[idx],     make_float4(Y[0], Y[1], Y[2], Y[3]));
        __stcs(&ctx.Y4[idx + 1], make_float4(Y[4], Y[5], Y[6], Y[7]));
    }
}

__global__ void __launch_bounds__(THREADS, 1)   // allow ptxas up to 255 regs
pscan_kernel(const float* __restrict__ Ag, const float* __restrict__ Xg,
             float* __restrict__ Yg) {
    const int lane = threadIdx.x;
    const int c = lane & (CT - 1);
    const int g = lane >> 2;            // log2(CT) = 2
    const int b = blockIdx.y;
    const int c0 = blockIdx.x * CT;

    Ctx ctx;
    ctx.A4 = (const float4*)Ag;
    ctx.X4 = (const float4*)Xg;
    ctx.Y4 = (float4*)Yg;
    ctx.g = g;
    // f4 index of this lane's (channel, first-row-of-its-chunk) at piece 0
    ctx.base = (b * LL + g * EPT) * (CC * 2) + (c0 + c) * 2;

    float carry[8];
#pragma unroll
    for (int k = 0; k < 8; k++) carry[k] = 0.f;

    float A0[EPT][8], X0[EPT][8], A1[EPT][8], X1[EPT][8];

    // prologue: piece 0 into buf0
    load_piece(ctx, 0, A0, X0);

#pragma unroll 1
    for (int p = 0; p < PIECES; p += 2) {
        // prefetch p+1 into buf1 while computing p from buf0
        load_piece(ctx, p + 1, A1, X1);
        compute_piece(ctx, p, A0, X0, carry);
        // prefetch p+2 into buf0 while computing p+1 from buf1
        if (p + 2 < PIECES) load_piece(ctx, p + 2, A0, X0);
        compute_piece(ctx, p + 1, A1, X1, carry);
    }
}

extern "C" void kernel_launch(void* const* d_in, const int* in_sizes, int n_in,
                              void* d_out, int out_size) {
    const float* A = (const float*)d_in[0];
    const float* X = (const float*)d_in[1];
    float* Y = (float*)d_out;

    dim3 grid(CC / CT, BB);   // 256 x 4 = 1024 one-warp CTAs
    pscan_kernel<<<grid, THREADS>>>(A, X, Y);
}